// round 10
// baseline (speedup 1.0000x reference)
#include <cuda_runtime.h>
#include <cuda_bf16.h>
#include <cuda_fp16.h>
#include <math.h>
#include <stdint.h>

// Problem constants (fixed by setup_inputs)
#define SEQ   4096
#define HID   2048
#define NHQ   32
#define NHKV  4
#define DH    128
#define DQTOT (NHQ*DH)    // 4096
#define DKVTOT (NHKV*DH)  // 512

// ---------------------------------------------------------------------------
// Scratch (device globals; no cudaMalloc allowed)
// ---------------------------------------------------------------------------
__device__ uint4 g_XhiQ[(HID/16) * (SEQ/16) * 32];   // a-frag quads bf16 hi, 16MB
__device__ uint4 g_XloQ[(HID/16) * (SEQ/16) * 32];   // 16MB
__device__ uint4 g_XhQ [(HID/16) * (SEQ/16) * 32];   // fp16 a-frag quads, 16MB
__device__ uint4 g_WqT[(HID/16) * DQTOT * 4];        // quad bf16 hi/lo, 32MB
__device__ uint4 g_WkT[(HID/16) * DKVTOT * 4];       // 4MB
__device__ uint2 g_WvT[(HID/16) * DKVTOT * 4];       // fp16 pairs, 2MB
__device__ uint2 g_WoT[(DQTOT/16) * HID * 4];        // 16MB
__device__ float g_Q [SEQ * DQTOT];                  // 64MB (pre-rope)
__device__ float g_K [SEQ * DKVTOT];                 // 8MB (pre-rope)
__device__ __nv_bfloat16 g_Qhi[SEQ * DQTOT];         // 32MB
__device__ __nv_bfloat16 g_Qlo[SEQ * DQTOT];         // 32MB
__device__ uint4 g_KP[NHKV * 8 * SEQ * 4];           // quad layout, 8MB
__device__ uint2 g_VP[NHKV * DH * (SEQ/16) * 4];     // fp16 pair layout, 4MB
__device__ uint4 g_OQ[(DQTOT/16) * (SEQ/16) * 32];   // O as fp16 a-frag quads, 32MB

// ---------------------------------------------------------------------------
// precision helpers
// ---------------------------------------------------------------------------
__device__ __forceinline__ void bsplit2(float x0, float x1, uint32_t& hi, uint32_t& lo) {
    __nv_bfloat162 h = __floats2bfloat162_rn(x0, x1);
    float r0 = x0 - __bfloat162float(h.x);
    float r1 = x1 - __bfloat162float(h.y);
    __nv_bfloat162 l = __floats2bfloat162_rn(r0, r1);
    hi = *(uint32_t*)&h;
    lo = *(uint32_t*)&l;
}
__device__ __forceinline__ uint32_t h2pack(float a, float b) {
    __half2 h = __floats2half2_rn(a, b);
    return *(uint32_t*)&h;
}
__device__ __forceinline__ void mma16b(float* c, const uint32_t* a, const uint32_t* b) {
    asm volatile(
        "mma.sync.aligned.m16n8k16.row.col.f32.bf16.bf16.f32 "
        "{%0,%1,%2,%3}, {%4,%5,%6,%7}, {%8,%9}, {%0,%1,%2,%3};\n"
        : "+f"(c[0]), "+f"(c[1]), "+f"(c[2]), "+f"(c[3])
        : "r"(a[0]), "r"(a[1]), "r"(a[2]), "r"(a[3]), "r"(b[0]), "r"(b[1]));
}
__device__ __forceinline__ void mma16h(float* c, const uint32_t* a, const uint32_t* b) {
    asm volatile(
        "mma.sync.aligned.m16n8k16.row.col.f32.f16.f16.f32 "
        "{%0,%1,%2,%3}, {%4,%5,%6,%7}, {%8,%9}, {%0,%1,%2,%3};\n"
        : "+f"(c[0]), "+f"(c[1]), "+f"(c[2]), "+f"(c[3])
        : "r"(a[0]), "r"(a[1]), "r"(a[2]), "r"(a[3]), "r"(b[0]), "r"(b[1]));
}
__device__ __forceinline__ void cp16(uint32_t dst, const void* src) {
    asm volatile("cp.async.ca.shared.global [%0], [%1], 16;\n" :: "r"(dst), "l"(src));
}
__device__ __forceinline__ void cp_commit() { asm volatile("cp.async.commit_group;\n"); }
__device__ __forceinline__ void cp_wait0()  { asm volatile("cp.async.wait_group 0;\n"); }
__device__ __forceinline__ void cp_wait1()  { asm volatile("cp.async.wait_group 1;\n"); }

// ===========================================================================
// prep kernels (one-time streaming)
// ===========================================================================
// X -> a-fragment quad layouts. One thread per quad:
// id = ((c*(SEQ/16) + rg)*8 + gid)*4 + tig; quad covers rows {16rg+gid, +8},
// cols {16c+2tig, +1, +8, +9}.
__global__ void prep_XQ(const float* __restrict__ X,
                        uint4* __restrict__ XhiQ, uint4* __restrict__ XloQ,
                        uint4* __restrict__ XhQ)
{
    int id  = blockIdx.x * 256 + threadIdx.x;
    int tig = id & 3;
    int gid = (id >> 2) & 7;
    int rg  = (id >> 5) & (SEQ/16 - 1);
    int c   = id >> 13;
    const float* p0 = X + (size_t)(rg * 16 + gid) * HID + c * 16 + 2 * tig;
    const float* p1 = p0 + (size_t)8 * HID;
    float2 a0 = *(const float2*)p0;
    float2 a1 = *(const float2*)p1;
    float2 a2 = *(const float2*)(p0 + 8);
    float2 a3 = *(const float2*)(p1 + 8);
    uint32_t h0,l0,h1,l1,h2_,l2,h3,l3;
    bsplit2(a0.x, a0.y, h0, l0);
    bsplit2(a1.x, a1.y, h1, l1);
    bsplit2(a2.x, a2.y, h2_, l2);
    bsplit2(a3.x, a3.y, h3, l3);
    XhiQ[id] = make_uint4(h0, h1, h2_, h3);
    XloQ[id] = make_uint4(l0, l1, l2, l3);
    XhQ[id]  = make_uint4(h2pack(a0.x, a0.y), h2pack(a1.x, a1.y),
                          h2pack(a2.x, a2.y), h2pack(a3.x, a3.y));
}

// quad layout for bf16x3 B-operand: out[(c*N + n)*4 + tg] = {hiA, hiB, loA, loB}
__global__ void prep_W3(const float* __restrict__ W, uint4* __restrict__ out,
                        int N, int nMask, int nShift)
{
    int id = blockIdx.x * 256 + threadIdx.x;
    int tg = id & 3;
    int n  = (id >> 2) & nMask;
    int c  = id >> (2 + nShift);
    const float* Wp = W + (size_t)(16 * c + 2 * tg) * N + n;
    uint32_t hA, lA, hB, lB;
    bsplit2(Wp[0],           Wp[(size_t)N],    hA, lA);
    bsplit2(Wp[(size_t)8*N], Wp[(size_t)9*N], hB, lB);
    out[id] = make_uint4(hA, hB, lA, lB);
}

// fp16 pair layout: out[(c*N + n)*4 + tg] = { h2(kpairA), h2(kpairB) }
__global__ void prep_W2(const float* __restrict__ W, uint2* __restrict__ out,
                        int N, int nMask, int nShift)
{
    int id = blockIdx.x * 256 + threadIdx.x;
    int tg = id & 3;
    int n  = (id >> 2) & nMask;
    int c  = id >> (2 + nShift);
    const float* Wp = W + (size_t)(16 * c + 2 * tg) * N + n;
    out[id] = make_uint2(h2pack(Wp[0],           Wp[(size_t)N]),
                         h2pack(Wp[(size_t)8*N], Wp[(size_t)9*N]));
}

// ===========================================================================
// gemm_bf3q: 3-term bf16 GEMM. A in a-frag quad layout (hi/lo), B quad.
// 128x128 tile, BK=32, 256 threads, double-buffered, all-LDS.128 fragments.
// ===========================================================================
// smem u32: AhiQ uint4[2][512] @0, AloQ @4096, BQ uint4[2][1024] @8192
#define G3Q_SMEM_BYTES (16384 * 4)   // 65536

__global__ __launch_bounds__(256, 2) void gemm_bf3q(
    const uint4* __restrict__ AhiQ, const uint4* __restrict__ AloQ,
    const uint4* __restrict__ Bq, float* __restrict__ C,
    int M, int N, int K)
{
    extern __shared__ uint32_t smq[];
    const uint32_t smBase = (uint32_t)__cvta_generic_to_shared(smq);

    const int tid  = threadIdx.x;
    const int lane = tid & 31;
    const int w    = tid >> 5;
    const int wm   = w >> 2;
    const int wn   = w & 3;
    const int m0   = blockIdx.y * 128;
    const int n0   = blockIdx.x * 128;
    const int gid  = lane >> 2;
    const int tig  = lane & 3;
    const int Mg   = M >> 4;
    const int rg0  = m0 >> 4;

    float c[4][4][4];
#pragma unroll
    for (int mt = 0; mt < 4; mt++)
#pragma unroll
        for (int nt = 0; nt < 4; nt++)
#pragma unroll
            for (int q = 0; q < 4; q++) c[mt][nt][q] = 0.f;

#define G3Q_LOAD(t, buf) do {                                                  \
    _Pragma("unroll")                                                          \
    for (int l = 0; l < 2; l++) {                                              \
        int task = tid + l * 256;                                              \
        int c2 = task >> 8, rg = (task >> 5) & 7, ln = task & 31;              \
        size_t src = ((size_t)((t) * 2 + c2) * Mg + rg0 + rg) * 32 + ln;       \
        uint32_t dst = ((buf) * 512 + c2 * 256 + rg * 32 + ln) * 16;           \
        cp16(smBase + dst,         AhiQ + src);                                \
        cp16(smBase + 16384 + dst, AloQ + src);                                \
    }                                                                          \
    _Pragma("unroll")                                                          \
    for (int l = 0; l < 4; l++) {                                              \
        int task = tid + l * 256;                                              \
        int c2 = task >> 9, n = (task >> 2) & 127, tg = task & 3;              \
        cp16(smBase + 32768 + ((buf) * 1024 + (c2 * 128 + n) * 4 + tg) * 16,   \
             Bq + ((size_t)((t) * 2 + c2) * N + n0 + n) * 4 + tg);             \
    }                                                                          \
    cp_commit();                                                               \
} while (0)

    const uint4* AhiS = (const uint4*)smq;
    const uint4* AloS = (const uint4*)(smq + 4096);
    const uint4* BqS  = (const uint4*)(smq + 8192);

    const int NT = K / 32;
    G3Q_LOAD(0, 0);

    for (int t = 0; t < NT; t++) {
        cp_wait0();
        __syncthreads();
        if (t + 1 < NT) G3Q_LOAD(t + 1, (t + 1) & 1);
        const int buf = t & 1;

#pragma unroll
        for (int c2 = 0; c2 < 2; c2++) {
            uint32_t ahi[4][4], alo[4][4];
#pragma unroll
            for (int mt = 0; mt < 4; mt++) {
                uint4 va = AhiS[buf * 512 + c2 * 256 + (wm * 4 + mt) * 32 + lane];
                ahi[mt][0] = va.x; ahi[mt][1] = va.y; ahi[mt][2] = va.z; ahi[mt][3] = va.w;
                uint4 vl = AloS[buf * 512 + c2 * 256 + (wm * 4 + mt) * 32 + lane];
                alo[mt][0] = vl.x; alo[mt][1] = vl.y; alo[mt][2] = vl.z; alo[mt][3] = vl.w;
            }
#pragma unroll
            for (int nt = 0; nt < 4; nt++) {
                int nc = wn * 32 + nt * 8 + gid;
                uint4 bq = BqS[buf * 1024 + c2 * 512 + nc * 4 + tig];
                uint32_t bhi[2] = { bq.x, bq.y };
                uint32_t blo[2] = { bq.z, bq.w };
#pragma unroll
                for (int mt = 0; mt < 4; mt++) {
                    mma16b(c[mt][nt], ahi[mt], bhi);
                    mma16b(c[mt][nt], ahi[mt], blo);
                    mma16b(c[mt][nt], alo[mt], bhi);
                }
            }
        }
    }

#pragma unroll
    for (int mt = 0; mt < 4; mt++)
#pragma unroll
        for (int nt = 0; nt < 4; nt++) {
            int row = m0 + wm * 64 + mt * 16 + gid;
            int col = n0 + wn * 32 + nt * 8 + 2 * tig;
            *(float2*)&C[(size_t)row * N + col] = make_float2(c[mt][nt][0], c[mt][nt][1]);
            *(float2*)&C[(size_t)(row + 8) * N + col] = make_float2(c[mt][nt][2], c[mt][nt][3]);
        }
}

// ===========================================================================
// gemm_f16q: single-pass fp16 GEMM. A in a-frag quad layout, B uint2 pairs.
// VPACK=true: epilogue writes transposed fp16-pair-packed V (g_VP).
// ===========================================================================
// smem u32: AQ uint4[2][512] @0, B2 uint2[2][1024] @4096; VPACK stage 8448 @0
#define F16Q_SMEM_BYTES (8448 * 4)   // 33792

template<bool VPACK>
__global__ __launch_bounds__(256, 2) void gemm_f16q(
    const uint4* __restrict__ AQ, const uint2* __restrict__ B2,
    float* __restrict__ C, uint2* __restrict__ VP,
    int M, int N, int K)
{
    extern __shared__ uint32_t smq[];
    const uint32_t smBase = (uint32_t)__cvta_generic_to_shared(smq);

    const int tid  = threadIdx.x;
    const int lane = tid & 31;
    const int w    = tid >> 5;
    const int wm   = w >> 2;
    const int wn   = w & 3;
    const int m0   = blockIdx.y * 128;
    const int n0   = blockIdx.x * 128;
    const int gid  = lane >> 2;
    const int tig  = lane & 3;
    const int Mg   = M >> 4;
    const int rg0  = m0 >> 4;

    float c[4][4][4];
#pragma unroll
    for (int mt = 0; mt < 4; mt++)
#pragma unroll
        for (int nt = 0; nt < 4; nt++)
#pragma unroll
            for (int q = 0; q < 4; q++) c[mt][nt][q] = 0.f;

#define F16Q_LOAD(t, buf) do {                                                 \
    _Pragma("unroll")                                                          \
    for (int l = 0; l < 2; l++) {                                              \
        int task = tid + l * 256;                                              \
        int c2 = task >> 8, rg = (task >> 5) & 7, ln = task & 31;              \
        cp16(smBase + ((buf) * 512 + c2 * 256 + rg * 32 + ln) * 16,            \
             AQ + ((size_t)((t) * 2 + c2) * Mg + rg0 + rg) * 32 + ln);         \
    }                                                                          \
    _Pragma("unroll")                                                          \
    for (int l = 0; l < 2; l++) {                                              \
        int task = tid + l * 256;                                              \
        int c2 = task >> 8, n = (task >> 1) & 127, hf = task & 1;              \
        cp16(smBase + 16384 + ((buf) * 1024 + (c2 * 128 + n) * 4 + hf * 2) * 8,\
             B2 + ((size_t)((t) * 2 + c2) * N + n0 + n) * 4 + hf * 2);         \
    }                                                                          \
    cp_commit();                                                               \
} while (0)

    const uint4* AQS = (const uint4*)smq;
    const uint2* B2S = (const uint2*)(smq + 4096);

    const int NT = K / 32;
    F16Q_LOAD(0, 0);

    for (int t = 0; t < NT; t++) {
        cp_wait0();
        __syncthreads();
        if (t + 1 < NT) F16Q_LOAD(t + 1, (t + 1) & 1);
        const int buf = t & 1;

#pragma unroll
        for (int c2 = 0; c2 < 2; c2++) {
            uint32_t a[4][4];
#pragma unroll
            for (int mt = 0; mt < 4; mt++) {
                uint4 va = AQS[buf * 512 + c2 * 256 + (wm * 4 + mt) * 32 + lane];
                a[mt][0] = va.x; a[mt][1] = va.y; a[mt][2] = va.z; a[mt][3] = va.w;
            }
#pragma unroll
            for (int nt = 0; nt < 4; nt++) {
                int nc = wn * 32 + nt * 8 + gid;
                uint2 bu = B2S[buf * 1024 + c2 * 512 + nc * 4 + tig];
                uint32_t b[2] = { bu.x, bu.y };
#pragma unroll
                for (int mt = 0; mt < 4; mt++)
                    mma16h(c[mt][nt], a[mt], b);
            }
        }
    }

    if (!VPACK) {
#pragma unroll
        for (int mt = 0; mt < 4; mt++)
#pragma unroll
            for (int nt = 0; nt < 4; nt++) {
                int row = m0 + wm * 64 + mt * 16 + gid;
                int col = n0 + wn * 32 + nt * 8 + 2 * tig;
                *(float2*)&C[(size_t)row * N + col] = make_float2(c[mt][nt][0], c[mt][nt][1]);
                *(float2*)&C[(size_t)(row + 8) * N + col] = make_float2(c[mt][nt][2], c[mt][nt][3]);
            }
    } else {
        // stage tile as fp16 [128 s][132 d], then write transposed pair-packed VP
        __syncthreads();
        uint32_t* stage = smq;   // 128*66 = 8448 u32
#pragma unroll
        for (int mt = 0; mt < 4; mt++)
#pragma unroll
            for (int nt = 0; nt < 4; nt++) {
                int rm = wm * 64 + mt * 16 + gid;
                int cu = wn * 16 + nt * 4 + tig;
                stage[rm * 66 + cu]       = h2pack(c[mt][nt][0], c[mt][nt][1]);
                stage[(rm + 8) * 66 + cu] = h2pack(c[mt][nt][2], c[mt][nt][3]);
            }
        __syncthreads();
        const __half* stageH = (const __half*)stage;
        int hk  = n0 >> 7;
        int jg0 = m0 >> 4;
#pragma unroll
        for (int i = 0; i < 16; i++) {
            int task = tid + i * 256;
            int d  = task >> 5;
            int jl = (task >> 2) & 7;
            int tg = task & 3;
            int s  = 16 * jl + 2 * tg;
            __half2 pA = __halves2half2(stageH[s * 132 + d],       stageH[(s + 1) * 132 + d]);
            __half2 pB = __halves2half2(stageH[(s + 8) * 132 + d], stageH[(s + 9) * 132 + d]);
            uint2 u = make_uint2(*(uint32_t*)&pA, *(uint32_t*)&pB);
            VP[((size_t)(hk * 128 + d) * 256 + jg0 + jl) * 4 + tg] = u;
        }
    }
}

// ---------------------------------------------------------------------------
// rope_q: g_Q f32 -> Qhi/Qlo bf16 row-major (scale folded).
// ---------------------------------------------------------------------------
__global__ void rope_q(const float* __restrict__ Q, const int* __restrict__ pos,
                       __nv_bfloat16* __restrict__ Qhi, __nv_bfloat16* __restrict__ Qlo)
{
    const int si = threadIdx.x >> 6;
    const int d  = threadIdx.x & 63;
    const int s  = blockIdx.x * 4 + si;
    const int h  = blockIdx.y;
    const float SC = 0.08838834764831845f;

    float p = (float)pos[s];
    float inv = powf(10000.0f, -(float)d / 64.0f);
    float sn, cs;
    sincosf(p * inv, &sn, &cs);

    size_t idx = (size_t)s * DQTOT + h * DH;
    float x1 = Q[idx + d];
    float x2 = Q[idx + d + 64];
    float o1 = (x1 * cs - x2 * sn) * SC;
    float o2 = (x2 * cs + x1 * sn) * SC;

    __nv_bfloat16 h1 = __float2bfloat16(o1);
    __nv_bfloat16 h2v = __float2bfloat16(o2);
    Qhi[idx + d]      = h1;
    Qlo[idx + d]      = __float2bfloat16(o1 - __bfloat162float(h1));
    Qhi[idx + d + 64] = h2v;
    Qlo[idx + d + 64] = __float2bfloat16(o2 - __bfloat162float(h2v));
}

// ---------------------------------------------------------------------------
// rope_k: g_K f32 -> g_KP quad layout.
// ---------------------------------------------------------------------------
__global__ void rope_k(const float* __restrict__ K, const int* __restrict__ pos,
                       uint4* __restrict__ KP)
{
    const int j  = threadIdx.x & 31;
    const int si = threadIdx.x >> 5;
    const int s  = blockIdx.x * 4 + si;
    const int hk = blockIdx.y;

    float p = (float)pos[s];
    float inv0 = powf(10000.0f, -(float)(2 * j)     / 64.0f);
    float inv1 = powf(10000.0f, -(float)(2 * j + 1) / 64.0f);
    float s0, c0, s1, c1;
    sincosf(p * inv0, &s0, &c0);
    sincosf(p * inv1, &s1, &c1);

    const float* base = K + (size_t)s * DKVTOT + hk * DH;
    float aL0 = base[2 * j],      aL1 = base[2 * j + 1];
    float aH0 = base[2 * j + 64], aH1 = base[2 * j + 65];

    float oL0 = aL0 * c0 - aH0 * s0;
    float oL1 = aL1 * c1 - aH1 * s1;
    float oH0 = aH0 * c0 + aL0 * s0;
    float oH1 = aH1 * c1 + aL1 * s1;

    uint32_t hL, lL, hH, lH;
    bsplit2(oL0, oL1, hL, lL);
    bsplit2(oH0, oH1, hH, lH);

    int cL = j >> 3;
    int tg = j & 3;
    int slot = (j >> 2) & 1;
    uint32_t* q1 = (uint32_t*)&KP[((size_t)(hk * 8 + cL) * SEQ + s) * 4 + tg];
    q1[slot]     = hL;
    q1[2 + slot] = lL;
    uint32_t* q2 = (uint32_t*)&KP[((size_t)(hk * 8 + 4 + cL) * SEQ + s) * 4 + tg];
    q2[slot]     = hH;
    q2[2 + slot] = lH;
}

// ===========================================================================
// flash_mma: 128 q-rows x 64-wide KV tiles, 8 warps.
// QK bf16x3, no-max softmax (exp direct; scores bounded), P register-resident
// (S C-frag == PV A-frag lane mapping), PV fp16. O written as a-frag quads.
// ===========================================================================
// smem u32: KSP uint4[2][2048] @0 (16384), VSP uint2[2][2560] @16384 (10240)
#define FL_SMEM_BYTES (26624 * 4)   // 106496

__global__ __launch_bounds__(256, 1) void flash_mma(
    const uint32_t* __restrict__ Qhi, const uint32_t* __restrict__ Qlo,
    const uint4* __restrict__ KP, const uint2* __restrict__ VP,
    uint4* __restrict__ OQ)
{
    extern __shared__ uint32_t sm[];
    const uint32_t smBase = (uint32_t)__cvta_generic_to_shared(sm);

    const int qb   = (gridDim.x - 1) - blockIdx.x;   // heavy blocks first
    const int h    = blockIdx.y;
    const int hk   = h >> 3;
    const int tid  = threadIdx.x;
    const int lane = tid & 31;
    const int w    = tid >> 5;
    const int gid  = lane >> 2;
    const int tig  = lane & 3;
    const int r0   = w * 16 + gid;
    const int r0g  = qb * 128 + r0;

    // Q fragments: direct LDG from pre-split bf16 (row pitch 2048 u32)
    uint32_t qhi[8][4], qlo[8][4];
#pragma unroll
    for (int c = 0; c < 8; c++) {
        size_t i0 = (size_t)r0g * 2048 + h * 64 + c * 8 + tig;
        qhi[c][0] = Qhi[i0];           qhi[c][1] = Qhi[i0 + 8 * 2048];
        qhi[c][2] = Qhi[i0 + 4];       qhi[c][3] = Qhi[i0 + 8 * 2048 + 4];
        qlo[c][0] = Qlo[i0];           qlo[c][1] = Qlo[i0 + 8 * 2048];
        qlo[c][2] = Qlo[i0 + 4];       qlo[c][3] = Qlo[i0 + 8 * 2048 + 4];
    }

#define FL_ISSUE(kb, buf) do {                                                 \
    _Pragma("unroll")                                                          \
    for (int l = 0; l < 8; l++) {                                              \
        int task = tid + l * 256;                                              \
        int cc = task >> 8, ss = (task >> 2) & 63, tg = task & 3;              \
        cp16(smBase + ((buf) * 8192 + ((cc * 64 + ss) * 4 + tg) * 4) * 4,      \
             KP + ((size_t)(hk * 8 + cc) * SEQ + (kb) * 64 + ss) * 4 + tg);    \
    }                                                                          \
    _Pragma("unroll")                                                          \
    for (int l = 0; l < 4; l++) {                                              \
        int task = tid + l * 256;                                              \
        int dd = task >> 3, jj = (task >> 1) & 3, hf = task & 1;               \
        cp16(smBase + (16384 + (buf) * 5120 + (dd * 20 + jj * 4 + hf * 2) * 2) * 4, \
             VP + ((size_t)(hk * 128 + dd) * 256 + (kb) * 4 + jj) * 4 + hf * 2); \
    }                                                                          \
    cp_commit();                                                               \
} while (0)

    float l_[2] = { 0.f, 0.f };
    float o[16][4];
#pragma unroll
    for (int nt = 0; nt < 16; nt++)
#pragma unroll
        for (int q = 0; q < 4; q++) o[nt][q] = 0.f;

    const int kbmax = 2 * qb + 1;
    FL_ISSUE(0, 0);

    for (int kb = 0; kb <= kbmax; kb++) {
        __syncthreads();   // all warps done with buffer being overwritten next
        if (kb < kbmax) { FL_ISSUE(kb + 1, (kb + 1) & 1); cp_wait1(); }
        else             cp_wait0();
        __syncthreads();   // buf[kb] ready for all

        const int buf = kb & 1;
        const uint4* Ksp = (const uint4*)sm + buf * 2048;
        const uint2* Vsp = (const uint2*)(sm + 16384) + buf * 2560;

        // S = Q K^T (bf16x3), warp: 16 rows x 64 cols
        float s[8][4];
#pragma unroll
        for (int nt = 0; nt < 8; nt++)
#pragma unroll
            for (int q = 0; q < 4; q++) s[nt][q] = 0.f;

#pragma unroll
        for (int c = 0; c < 8; c++) {
            const uint4* kbase = Ksp + c * 256 + tig;
#pragma unroll
            for (int nt = 0; nt < 8; nt++) {
                uint4 kf = kbase[(nt * 8 + gid) * 4];
                uint32_t bhi[2] = { kf.x, kf.y };
                uint32_t blo[2] = { kf.z, kf.w };
                mma16b(s[nt], qhi[c], bhi);
                mma16b(s[nt], qhi[c], blo);
                mma16b(s[nt], qlo[c], bhi);
            }
        }

        // causal mask (only near-diagonal tiles)
        if (kb >= 2 * qb) {
#pragma unroll
            for (int nt = 0; nt < 8; nt++) {
                int col = kb * 64 + nt * 8 + 2 * tig;
                if (col     > r0g)     s[nt][0] = -1e30f;
                if (col + 1 > r0g)     s[nt][1] = -1e30f;
                if (col     > r0g + 8) s[nt][2] = -1e30f;
                if (col + 1 > r0g + 8) s[nt][3] = -1e30f;
            }
        }

        // softmax without max-shift (scores bounded; masked -> exp = 0).
        // S C-fragment maps lane-for-lane onto PV A-fragment: P stays in regs.
        float rs0 = 0.f, rs1 = 0.f;
        uint32_t pa[4][4];
#pragma unroll
        for (int j = 0; j < 4; j++) {
            float e00 = __expf(s[2*j][0]),   e01 = __expf(s[2*j][1]);
            float e02 = __expf(s[2*j][2]),   e03 = __expf(s[2*j][3]);
            float e10 = __expf(s[2*j+1][0]), e11 = __expf(s[2*j+1][1]);
            float e12 = __expf(s[2*j+1][2]), e13 = __expf(s[2*j+1][3]);
            rs0 += (e00 + e01) + (e10 + e11);
            rs1 += (e02 + e03) + (e12 + e13);
            pa[j][0] = h2pack(e00, e01);
            pa[j][1] = h2pack(e02, e03);
            pa[j][2] = h2pack(e10, e11);
            pa[j][3] = h2pack(e12, e13);
        }
        rs0 += __shfl_xor_sync(0xffffffffu, rs0, 1);
        rs0 += __shfl_xor_sync(0xffffffffu, rs0, 2);
        rs1 += __shfl_xor_sync(0xffffffffu, rs1, 1);
        rs1 += __shfl_xor_sync(0xffffffffu, rs1, 2);
        l_[0] += rs0;
        l_[1] += rs1;

        // O += P @ V (fp16; warp: 16 rows x 128 cols, 4 k16 chunks)
#pragma unroll
        for (int j = 0; j < 4; j++) {
#pragma unroll
            for (int nt = 0; nt < 16; nt++) {
                uint2 vv = Vsp[(nt * 8 + gid) * 20 + j * 4 + tig];
                uint32_t b[2] = { vv.x, vv.y };
                mma16h(o[nt], pa[j], b);
            }
        }
    }

    // epilogue: normalize, store as fp16 a-frag quads for the Wo GEMM
    {
        const float il0 = 1.0f / l_[0];
        const float il1 = 1.0f / l_[1];
        const int rgO = qb * 8 + w;
#pragma unroll
        for (int j = 0; j < 8; j++) {
            int c = h * 8 + j;
            uint4 u;
            u.x = h2pack(o[2*j][0]   * il0, o[2*j][1]   * il0);
            u.y = h2pack(o[2*j][2]   * il1, o[2*j][3]   * il1);
            u.z = h2pack(o[2*j+1][0] * il0, o[2*j+1][1] * il0);
            u.w = h2pack(o[2*j+1][2] * il1, o[2*j+1][3] * il1);
            OQ[((size_t)(c * 256 + rgO) * 8 + gid) * 4 + tig] = u;
        }
    }
}

// ---------------------------------------------------------------------------
// Launch
// ---------------------------------------------------------------------------
extern "C" void kernel_launch(void* const* d_in, const int* in_sizes, int n_in,
                              void* d_out, int out_size)
{
    const float* X  = (const float*)d_in[0];
    const float* Wq = (const float*)d_in[1];
    const float* Wk = (const float*)d_in[2];
    const float* Wv = (const float*)d_in[3];
    const float* Wo = (const float*)d_in[4];
    const int*  pos = (const int*)d_in[5];
    float* out = (float*)d_out;

    uint4 *XhiQ, *XloQ, *XhQ, *WqT, *WkT, *KPp, *OQp;
    uint2 *WvT, *WoT, *VPp;
    float *Qp, *Kp;
    __nv_bfloat16 *Qhi, *Qlo;
    cudaGetSymbolAddress((void**)&XhiQ, g_XhiQ);
    cudaGetSymbolAddress((void**)&XloQ, g_XloQ);
    cudaGetSymbolAddress((void**)&XhQ,  g_XhQ);
    cudaGetSymbolAddress((void**)&WqT,  g_WqT);
    cudaGetSymbolAddress((void**)&WkT,  g_WkT);
    cudaGetSymbolAddress((void**)&WvT,  g_WvT);
    cudaGetSymbolAddress((void**)&WoT,  g_WoT);
    cudaGetSymbolAddress((void**)&Qp,   g_Q);
    cudaGetSymbolAddress((void**)&Kp,   g_K);
    cudaGetSymbolAddress((void**)&Qhi,  g_Qhi);
    cudaGetSymbolAddress((void**)&Qlo,  g_Qlo);
    cudaGetSymbolAddress((void**)&KPp,  g_KP);
    cudaGetSymbolAddress((void**)&VPp,  g_VP);
    cudaGetSymbolAddress((void**)&OQp,  g_OQ);

    cudaFuncSetAttribute(gemm_bf3q, cudaFuncAttributeMaxDynamicSharedMemorySize,
                         G3Q_SMEM_BYTES);
    cudaFuncSetAttribute(gemm_f16q<false>, cudaFuncAttributeMaxDynamicSharedMemorySize,
                         F16Q_SMEM_BYTES);
    cudaFuncSetAttribute(gemm_f16q<true>, cudaFuncAttributeMaxDynamicSharedMemorySize,
                         F16Q_SMEM_BYTES);
    cudaFuncSetAttribute(flash_mma, cudaFuncAttributeMaxDynamicSharedMemorySize,
                         FL_SMEM_BYTES);

    // one-time operand prep
    prep_XQ<<<(HID/16) * (SEQ/16) * 32 / 256, 256>>>(X, XhiQ, XloQ, XhQ);
    prep_W3<<<(HID/16) * DQTOT * 4 / 256, 256>>>(Wq, WqT, DQTOT, DQTOT - 1, 12);
    prep_W3<<<(HID/16) * DKVTOT * 4 / 256, 256>>>(Wk, WkT, DKVTOT, DKVTOT - 1, 9);
    prep_W2<<<(HID/16) * DKVTOT * 4 / 256, 256>>>(Wv, WvT, DKVTOT, DKVTOT - 1, 9);
    prep_W2<<<(DQTOT/16) * HID * 4 / 256, 256>>>(Wo, WoT, HID, HID - 1, 11);

    // projections
    gemm_bf3q<<<dim3(DQTOT / 128, SEQ / 128), 256, G3Q_SMEM_BYTES>>>(
        XhiQ, XloQ, WqT, Qp, SEQ, DQTOT, HID);
    gemm_bf3q<<<dim3(DKVTOT / 128, SEQ / 128), 256, G3Q_SMEM_BYTES>>>(
        XhiQ, XloQ, WkT, Kp, SEQ, DKVTOT, HID);
    gemm_f16q<true><<<dim3(DKVTOT / 128, SEQ / 128), 256, F16Q_SMEM_BYTES>>>(
        XhQ, WvT, nullptr, VPp, SEQ, DKVTOT, HID);

    // RoPE + split/pack
    rope_q<<<dim3(SEQ / 4, NHQ), 256>>>(Qp, pos, Qhi, Qlo);
    rope_k<<<dim3(SEQ / 4, NHKV), 128>>>(Kp, pos, KPp);

    // causal flash attention
    flash_mma<<<dim3(SEQ / 128, NHQ), 256, FL_SMEM_BYTES>>>(
        (const uint32_t*)Qhi, (const uint32_t*)Qlo, KPp, VPp, OQp);

    // output projection (A = O in quad layout)
    gemm_f16q<false><<<dim3(HID / 128, SEQ / 128), 256, F16Q_SMEM_BYTES>>>(
        OQp, WoT, out, nullptr, SEQ, HID, DQTOT);
}

// round 13
// speedup vs baseline: 1.0018x; 1.0018x over previous
#include <cuda_runtime.h>
#include <cuda_bf16.h>
#include <cuda_fp16.h>
#include <math.h>
#include <stdint.h>

#define SEQ   4096
#define HID   2048
#define NHQ   32
#define NHKV  4
#define DH    128
#define DQTOT (NHQ*DH)
#define DKVTOT (NHKV*DH)

// ---------------- scratch ----------------
__device__ uint4 g_XhiQ[(HID/16) * (SEQ/16) * 32];
__device__ uint4 g_XloQ[(HID/16) * (SEQ/16) * 32];
__device__ uint4 g_XhQ [(HID/16) * (SEQ/16) * 32];
__device__ uint4 g_WqT[(HID/16) * DQTOT * 4];
__device__ uint4 g_WkT[(HID/16) * DKVTOT * 4];
__device__ uint2 g_WvT[(HID/16) * DKVTOT * 4];
__device__ uint2 g_WoT[(DQTOT/16) * HID * 4];
__device__ __nv_bfloat16 g_Qhi[SEQ * DQTOT];
__device__ __nv_bfloat16 g_Qlo[SEQ * DQTOT];
__device__ uint4 g_KP[NHKV * 8 * SEQ * 4];
__device__ uint2 g_VP[NHKV * DH * (SEQ/16) * 4];
__device__ uint4 g_OQ[(DQTOT/16) * (SEQ/16) * 32];

// ---------------- helpers ----------------
__device__ __forceinline__ void bsplit2(float x0, float x1, uint32_t& hi, uint32_t& lo) {
    __nv_bfloat162 h = __floats2bfloat162_rn(x0, x1);
    float r0 = x0 - __bfloat162float(h.x);
    float r1 = x1 - __bfloat162float(h.y);
    __nv_bfloat162 l = __floats2bfloat162_rn(r0, r1);
    hi = *(uint32_t*)&h; lo = *(uint32_t*)&l;
}
__device__ __forceinline__ uint32_t h2pack(float a, float b) {
    __half2 h = __floats2half2_rn(a, b);
    return *(uint32_t*)&h;
}
__device__ __forceinline__ void mma16b(float* c, const uint32_t* a, const uint32_t* b) {
    asm volatile("mma.sync.aligned.m16n8k16.row.col.f32.bf16.bf16.f32 "
        "{%0,%1,%2,%3}, {%4,%5,%6,%7}, {%8,%9}, {%0,%1,%2,%3};\n"
        : "+f"(c[0]), "+f"(c[1]), "+f"(c[2]), "+f"(c[3])
        : "r"(a[0]), "r"(a[1]), "r"(a[2]), "r"(a[3]), "r"(b[0]), "r"(b[1]));
}
__device__ __forceinline__ void mma16h(float* c, const uint32_t* a, const uint32_t* b) {
    asm volatile("mma.sync.aligned.m16n8k16.row.col.f32.f16.f16.f32 "
        "{%0,%1,%2,%3}, {%4,%5,%6,%7}, {%8,%9}, {%0,%1,%2,%3};\n"
        : "+f"(c[0]), "+f"(c[1]), "+f"(c[2]), "+f"(c[3])
        : "r"(a[0]), "r"(a[1]), "r"(a[2]), "r"(a[3]), "r"(b[0]), "r"(b[1]));
}
__device__ __forceinline__ void cp16(uint32_t dst, const void* src) {
    asm volatile("cp.async.ca.shared.global [%0], [%1], 16;\n" :: "r"(dst), "l"(src));
}
__device__ __forceinline__ void cp_commit() { asm volatile("cp.async.commit_group;\n"); }
__device__ __forceinline__ void cp_wait0()  { asm volatile("cp.async.wait_group 0;\n"); }
__device__ __forceinline__ void cp_wait1()  { asm volatile("cp.async.wait_group 1;\n"); }

// ---------------- prep kernels (identical numerics to R8) ----------------
__global__ void prep_XQ(const float* __restrict__ X,
                        uint4* __restrict__ XhiQ, uint4* __restrict__ XloQ,
                        uint4* __restrict__ XhQ)
{
    int id  = blockIdx.x * 256 + threadIdx.x;
    int tig = id & 3, gid = (id >> 2) & 7, rg = (id >> 5) & (SEQ/16 - 1), c = id >> 13;
    const float* p0 = X + (size_t)(rg * 16 + gid) * HID + c * 16 + 2 * tig;
    const float* p1 = p0 + (size_t)8 * HID;
    float2 a0 = *(const float2*)p0, a1 = *(const float2*)p1;
    float2 a2 = *(const float2*)(p0 + 8), a3 = *(const float2*)(p1 + 8);
    uint32_t h0,l0,h1,l1,h2_,l2,h3,l3;
    bsplit2(a0.x, a0.y, h0, l0);
    bsplit2(a1.x, a1.y, h1, l1);
    bsplit2(a2.x, a2.y, h2_, l2);
    bsplit2(a3.x, a3.y, h3, l3);
    XhiQ[id] = make_uint4(h0, h1, h2_, h3);
    XloQ[id] = make_uint4(l0, l1, l2, l3);
    XhQ[id]  = make_uint4(h2pack(a0.x, a0.y), h2pack(a1.x, a1.y),
                          h2pack(a2.x, a2.y), h2pack(a3.x, a3.y));
}
__global__ void prep_W3(const float* __restrict__ W, uint4* __restrict__ out,
                        int N, int nMask, int nShift)
{
    int id = blockIdx.x * 256 + threadIdx.x;
    int tg = id & 3, n = (id >> 2) & nMask, c = id >> (2 + nShift);
    const float* Wp = W + (size_t)(16 * c + 2 * tg) * N + n;
    uint32_t hA, lA, hB, lB;
    bsplit2(Wp[0],           Wp[(size_t)N],    hA, lA);
    bsplit2(Wp[(size_t)8*N], Wp[(size_t)9*N], hB, lB);
    out[id] = make_uint4(hA, hB, lA, lB);
}
__global__ void prep_W2(const float* __restrict__ W, uint2* __restrict__ out,
                        int N, int nMask, int nShift)
{
    int id = blockIdx.x * 256 + threadIdx.x;
    int tg = id & 3, n = (id >> 2) & nMask, c = id >> (2 + nShift);
    const float* Wp = W + (size_t)(16 * c + 2 * tg) * N + n;
    out[id] = make_uint2(h2pack(Wp[0],           Wp[(size_t)N]),
                         h2pack(Wp[(size_t)8*N], Wp[(size_t)9*N]));
}

// ===========================================================================
// gemm_bf3q<EPI>: bf16x3 GEMM (R8 mainloop) with fused epilogue.
// EPI=1: RoPE-Q -> Qhi/Qlo. EPI=2: RoPE-K -> KP quad layout.
// Tile 128x128, BK=32, 256 threads, double buffered. M=SEQ, K=HID.
// smem: pipeline 65536 B; f32 epilogue stage 128x132 = 67584 B.
// ===========================================================================
#define G3Q_SMEM_BYTES 67584

template<int EPI>
__global__ __launch_bounds__(256, 2) void gemm_bf3q(
    const uint4* __restrict__ AhiQ, const uint4* __restrict__ AloQ,
    const uint4* __restrict__ Bq, const int* __restrict__ pos,
    __nv_bfloat16* __restrict__ Qhi, __nv_bfloat16* __restrict__ Qlo,
    uint4* __restrict__ KP, int N)
{
    extern __shared__ uint32_t smq[];
    const uint32_t smBase = (uint32_t)__cvta_generic_to_shared(smq);

    const int tid = threadIdx.x, lane = tid & 31, w = tid >> 5;
    const int wm = w >> 2, wn = w & 3;
    const int hb = blockIdx.x;            // head index (N-tile)
    const int m0 = blockIdx.y * 128;
    const int n0 = hb * 128;
    const int gid = lane >> 2, tig = lane & 3;
    const int rg0 = m0 >> 4;

    float c[4][4][4];
#pragma unroll
    for (int mt = 0; mt < 4; mt++)
#pragma unroll
        for (int nt = 0; nt < 4; nt++)
#pragma unroll
            for (int q = 0; q < 4; q++) c[mt][nt][q] = 0.f;

#define G3Q_LOAD(t, buf) do {                                                  \
    _Pragma("unroll")                                                          \
    for (int l = 0; l < 2; l++) {                                              \
        int task = tid + l * 256;                                              \
        int c2 = task >> 8, rg = (task >> 5) & 7, ln = task & 31;              \
        size_t src = ((size_t)((t) * 2 + c2) * 256 + rg0 + rg) * 32 + ln;      \
        uint32_t dst = ((buf) * 512 + c2 * 256 + rg * 32 + ln) * 16;           \
        cp16(smBase + dst,         AhiQ + src);                                \
        cp16(smBase + 16384 + dst, AloQ + src);                                \
    }                                                                          \
    _Pragma("unroll")                                                          \
    for (int l = 0; l < 4; l++) {                                              \
        int task = tid + l * 256;                                              \
        int c2 = task >> 9, n = (task >> 2) & 127, tg = task & 3;              \
        cp16(smBase + 32768 + ((buf) * 1024 + (c2 * 128 + n) * 4 + tg) * 16,   \
             Bq + ((size_t)((t) * 2 + c2) * N + n0 + n) * 4 + tg);             \
    }                                                                          \
    cp_commit();                                                               \
} while (0)

    const uint4* AhiS = (const uint4*)smq;
    const uint4* AloS = (const uint4*)(smq + 4096);
    const uint4* BqS  = (const uint4*)(smq + 8192);

    const int NT = HID / 32;
    G3Q_LOAD(0, 0);

    for (int t = 0; t < NT; t++) {
        cp_wait0();
        __syncthreads();
        if (t + 1 < NT) G3Q_LOAD(t + 1, (t + 1) & 1);
        const int buf = t & 1;
#pragma unroll
        for (int c2 = 0; c2 < 2; c2++) {
            uint32_t ahi[4][4], alo[4][4];
#pragma unroll
            for (int mt = 0; mt < 4; mt++) {
                uint4 va = AhiS[buf * 512 + c2 * 256 + (wm * 4 + mt) * 32 + lane];
                ahi[mt][0] = va.x; ahi[mt][1] = va.y; ahi[mt][2] = va.z; ahi[mt][3] = va.w;
                uint4 vl = AloS[buf * 512 + c2 * 256 + (wm * 4 + mt) * 32 + lane];
                alo[mt][0] = vl.x; alo[mt][1] = vl.y; alo[mt][2] = vl.z; alo[mt][3] = vl.w;
            }
#pragma unroll
            for (int nt = 0; nt < 4; nt++) {
                uint4 bq = BqS[buf * 1024 + c2 * 512 + (wn * 32 + nt * 8 + gid) * 4 + tig];
                uint32_t bhi[2] = { bq.x, bq.y };
                uint32_t blo[2] = { bq.z, bq.w };
#pragma unroll
                for (int mt = 0; mt < 4; mt++) {
                    mma16b(c[mt][nt], ahi[mt], bhi);
                    mma16b(c[mt][nt], ahi[mt], blo);
                    mma16b(c[mt][nt], alo[mt], bhi);
                }
            }
        }
    }

    // stage f32 tile
    __syncthreads();
    float* stage = (float*)smq;   // [128][132]
#pragma unroll
    for (int mt = 0; mt < 4; mt++)
#pragma unroll
        for (int nt = 0; nt < 4; nt++) {
            int row = wm * 64 + mt * 16 + gid;
            int col = wn * 32 + nt * 8 + 2 * tig;
            *(float2*)&stage[row * 132 + col] = make_float2(c[mt][nt][0], c[mt][nt][1]);
            *(float2*)&stage[(row + 8) * 132 + col] = make_float2(c[mt][nt][2], c[mt][nt][3]);
        }
    __syncthreads();

    if (EPI == 1) {
        // RoPE-Q + bf16 split, row-major out (scale folded)
        const float SC = 0.08838834764831845f;
        const int d  = tid & 63;
        const int rb = tid >> 6;
        const float inv = powf(10000.0f, -(float)d / 64.0f);
#pragma unroll 4
        for (int i = 0; i < 32; i++) {
            int r = rb + i * 4;
            int s = m0 + r;
            float p = (float)pos[s];
            float sn, cs; sincosf(p * inv, &sn, &cs);
            float x1 = stage[r * 132 + d];
            float x2 = stage[r * 132 + d + 64];
            float o1 = (x1 * cs - x2 * sn) * SC;
            float o2 = (x2 * cs + x1 * sn) * SC;
            size_t idx = (size_t)s * DQTOT + hb * DH;
            __nv_bfloat16 h1 = __float2bfloat16(o1);
            __nv_bfloat16 h2v = __float2bfloat16(o2);
            Qhi[idx + d]      = h1;
            Qlo[idx + d]      = __float2bfloat16(o1 - __bfloat162float(h1));
            Qhi[idx + d + 64] = h2v;
            Qlo[idx + d + 64] = __float2bfloat16(o2 - __bfloat162float(h2v));
        }
    } else {
        // RoPE-K + bf16 split into KP quad layout
        const int j  = tid & 31;
        const int rb = tid >> 5;
        const float inv0 = powf(10000.0f, -(float)(2 * j)     / 64.0f);
        const float inv1 = powf(10000.0f, -(float)(2 * j + 1) / 64.0f);
        const int cL = j >> 3, tg = j & 3, slot = (j >> 2) & 1;
#pragma unroll 4
        for (int i = 0; i < 16; i++) {
            int r = rb + i * 8;
            int s = m0 + r;
            float p = (float)pos[s];
            float s0, c0, s1, c1;
            sincosf(p * inv0, &s0, &c0);
            sincosf(p * inv1, &s1, &c1);
            float aL0 = stage[r * 132 + 2 * j],      aL1 = stage[r * 132 + 2 * j + 1];
            float aH0 = stage[r * 132 + 2 * j + 64], aH1 = stage[r * 132 + 2 * j + 65];
            float oL0 = aL0 * c0 - aH0 * s0;
            float oL1 = aL1 * c1 - aH1 * s1;
            float oH0 = aH0 * c0 + aL0 * s0;
            float oH1 = aH1 * c1 + aL1 * s1;
            uint32_t hL, lL, hH, lH;
            bsplit2(oL0, oL1, hL, lL);
            bsplit2(oH0, oH1, hH, lH);
            uint32_t* q1 = (uint32_t*)&KP[((size_t)(hb * 8 + cL) * SEQ + s) * 4 + tg];
            q1[slot] = hL; q1[2 + slot] = lL;
            uint32_t* q2 = (uint32_t*)&KP[((size_t)(hb * 8 + 4 + cL) * SEQ + s) * 4 + tg];
            q2[slot] = hH; q2[2 + slot] = lH;
        }
    }
}

// ===========================================================================
// gemm_f16q<VPACK>: fp16 GEMM (R8, unchanged)
// ===========================================================================
#define F16Q_SMEM_BYTES (8448 * 4)

template<bool VPACK>
__global__ __launch_bounds__(256, 2) void gemm_f16q(
    const uint4* __restrict__ AQ, const uint2* __restrict__ B2,
    float* __restrict__ C, uint2* __restrict__ VP,
    int M, int N, int K)
{
    extern __shared__ uint32_t smq[];
    const uint32_t smBase = (uint32_t)__cvta_generic_to_shared(smq);
    const int tid = threadIdx.x, lane = tid & 31, w = tid >> 5;
    const int wm = w >> 2, wn = w & 3;
    const int m0 = blockIdx.y * 128, n0 = blockIdx.x * 128;
    const int gid = lane >> 2, tig = lane & 3;
    const int Mg = M >> 4, rg0 = m0 >> 4;

    float c[4][4][4];
#pragma unroll
    for (int mt = 0; mt < 4; mt++)
#pragma unroll
        for (int nt = 0; nt < 4; nt++)
#pragma unroll
            for (int q = 0; q < 4; q++) c[mt][nt][q] = 0.f;

#define F16Q_LOAD(t, buf) do {                                                 \
    _Pragma("unroll")                                                          \
    for (int l = 0; l < 2; l++) {                                              \
        int task = tid + l * 256;                                              \
        int c2 = task >> 8, rg = (task >> 5) & 7, ln = task & 31;              \
        cp16(smBase + ((buf) * 512 + c2 * 256 + rg * 32 + ln) * 16,            \
             AQ + ((size_t)((t) * 2 + c2) * Mg + rg0 + rg) * 32 + ln);         \
    }                                                                          \
    _Pragma("unroll")                                                          \
    for (int l = 0; l < 2; l++) {                                              \
        int task = tid + l * 256;                                              \
        int c2 = task >> 8, n = (task >> 1) & 127, hf = task & 1;              \
        cp16(smBase + 16384 + ((buf) * 1024 + (c2 * 128 + n) * 4 + hf * 2) * 8,\
             B2 + ((size_t)((t) * 2 + c2) * N + n0 + n) * 4 + hf * 2);         \
    }                                                                          \
    cp_commit();                                                               \
} while (0)

    const uint4* AQS = (const uint4*)smq;
    const uint2* B2S = (const uint2*)(smq + 4096);
    const int NT = K / 32;
    F16Q_LOAD(0, 0);
    for (int t = 0; t < NT; t++) {
        cp_wait0();
        __syncthreads();
        if (t + 1 < NT) F16Q_LOAD(t + 1, (t + 1) & 1);
        const int buf = t & 1;
#pragma unroll
        for (int c2 = 0; c2 < 2; c2++) {
            uint32_t a[4][4];
#pragma unroll
            for (int mt = 0; mt < 4; mt++) {
                uint4 va = AQS[buf * 512 + c2 * 256 + (wm * 4 + mt) * 32 + lane];
                a[mt][0] = va.x; a[mt][1] = va.y; a[mt][2] = va.z; a[mt][3] = va.w;
            }
#pragma unroll
            for (int nt = 0; nt < 4; nt++) {
                int nc = wn * 32 + nt * 8 + gid;
                uint2 bu = B2S[buf * 1024 + c2 * 512 + nc * 4 + tig];
                uint32_t b[2] = { bu.x, bu.y };
#pragma unroll
                for (int mt = 0; mt < 4; mt++)
                    mma16h(c[mt][nt], a[mt], b);
            }
        }
    }

    if (!VPACK) {
#pragma unroll
        for (int mt = 0; mt < 4; mt++)
#pragma unroll
            for (int nt = 0; nt < 4; nt++) {
                int row = m0 + wm * 64 + mt * 16 + gid;
                int col = n0 + wn * 32 + nt * 8 + 2 * tig;
                *(float2*)&C[(size_t)row * N + col] = make_float2(c[mt][nt][0], c[mt][nt][1]);
                *(float2*)&C[(size_t)(row + 8) * N + col] = make_float2(c[mt][nt][2], c[mt][nt][3]);
            }
    } else {
        __syncthreads();
        uint32_t* stage = smq;
#pragma unroll
        for (int mt = 0; mt < 4; mt++)
#pragma unroll
            for (int nt = 0; nt < 4; nt++) {
                int rm = wm * 64 + mt * 16 + gid;
                int cu = wn * 16 + nt * 4 + tig;
                stage[rm * 66 + cu]       = h2pack(c[mt][nt][0], c[mt][nt][1]);
                stage[(rm + 8) * 66 + cu] = h2pack(c[mt][nt][2], c[mt][nt][3]);
            }
        __syncthreads();
        const __half* stageH = (const __half*)stage;
        int hk = n0 >> 7, jg0 = m0 >> 4;
#pragma unroll
        for (int i = 0; i < 16; i++) {
            int task = tid + i * 256;
            int d = task >> 5, jl = (task >> 2) & 7, tg = task & 3;
            int s = 16 * jl + 2 * tg;
            __half2 pA = __halves2half2(stageH[s * 132 + d],       stageH[(s + 1) * 132 + d]);
            __half2 pB = __halves2half2(stageH[(s + 8) * 132 + d], stageH[(s + 9) * 132 + d]);
            VP[((size_t)(hk * 128 + d) * 256 + jg0 + jl) * 4 + tg] =
                make_uint2(*(uint32_t*)&pA, *(uint32_t*)&pB);
        }
    }
}

// ===========================================================================
// flash_mma: unchanged from R8 (O -> a-frag quads)
// ===========================================================================
#define FL_SMEM_BYTES (26624 * 4)

__global__ __launch_bounds__(256, 1) void flash_mma(
    const uint32_t* __restrict__ Qhi, const uint32_t* __restrict__ Qlo,
    const uint4* __restrict__ KP, const uint2* __restrict__ VP,
    uint4* __restrict__ OQ)
{
    extern __shared__ uint32_t sm[];
    const uint32_t smBase = (uint32_t)__cvta_generic_to_shared(sm);
    const int qb = (gridDim.x - 1) - blockIdx.x;
    const int h = blockIdx.y, hk = h >> 3;
    const int tid = threadIdx.x, lane = tid & 31, w = tid >> 5;
    const int gid = lane >> 2, tig = lane & 3;
    const int r0 = w * 16 + gid, r0g = qb * 128 + r0;

    uint32_t qhi[8][4], qlo[8][4];
#pragma unroll
    for (int c = 0; c < 8; c++) {
        size_t i0 = (size_t)r0g * 2048 + h * 64 + c * 8 + tig;
        qhi[c][0] = Qhi[i0];     qhi[c][1] = Qhi[i0 + 8 * 2048];
        qhi[c][2] = Qhi[i0 + 4]; qhi[c][3] = Qhi[i0 + 8 * 2048 + 4];
        qlo[c][0] = Qlo[i0];     qlo[c][1] = Qlo[i0 + 8 * 2048];
        qlo[c][2] = Qlo[i0 + 4]; qlo[c][3] = Qlo[i0 + 8 * 2048 + 4];
    }

#define FL_ISSUE(kb, buf) do {                                                 \
    _Pragma("unroll")                                                          \
    for (int l = 0; l < 8; l++) {                                              \
        int task = tid + l * 256;                                              \
        int cc = task >> 8, ss = (task >> 2) & 63, tg = task & 3;              \
        cp16(smBase + ((buf) * 8192 + ((cc * 64 + ss) * 4 + tg) * 4) * 4,      \
             KP + ((size_t)(hk * 8 + cc) * SEQ + (kb) * 64 + ss) * 4 + tg);    \
    }                                                                          \
    _Pragma("unroll")                                                          \
    for (int l = 0; l < 4; l++) {                                              \
        int task = tid + l * 256;                                              \
        int dd = task >> 3, jj = (task >> 1) & 3, hf = task & 1;               \
        cp16(smBase + (16384 + (buf) * 5120 + (dd * 20 + jj * 4 + hf * 2) * 2) * 4, \
             VP + ((size_t)(hk * 128 + dd) * 256 + (kb) * 4 + jj) * 4 + hf * 2); \
    }                                                                          \
    cp_commit();                                                               \
} while (0)

    float l_[2] = { 0.f, 0.f };
    float o[16][4];
#pragma unroll
    for (int nt = 0; nt < 16; nt++)
#pragma unroll
        for (int q = 0; q < 4; q++) o[nt][q] = 0.f;

    const int kbmax = 2 * qb + 1;
    FL_ISSUE(0, 0);

    for (int kb = 0; kb <= kbmax; kb++) {
        __syncthreads();
        if (kb < kbmax) { FL_ISSUE(kb + 1, (kb + 1) & 1); cp_wait1(); }
        else             cp_wait0();
        __syncthreads();

        const int buf = kb & 1;
        const uint4* Ksp = (const uint4*)sm + buf * 2048;
        const uint2* Vsp = (const uint2*)(sm + 16384) + buf * 2560;

        float s[8][4];
#pragma unroll
        for (int nt = 0; nt < 8; nt++)
#pragma unroll
            for (int q = 0; q < 4; q++) s[nt][q] = 0.f;
#pragma unroll
        for (int c = 0; c < 8; c++) {
            const uint4* kbase = Ksp + c * 256 + tig;
#pragma unroll
            for (int nt = 0; nt < 8; nt++) {
                uint4 kf = kbase[(nt * 8 + gid) * 4];
                uint32_t bhi[2] = { kf.x, kf.y };
                uint32_t blo[2] = { kf.z, kf.w };
                mma16b(s[nt], qhi[c], bhi);
                mma16b(s[nt], qhi[c], blo);
                mma16b(s[nt], qlo[c], bhi);
            }
        }
        if (kb >= 2 * qb) {
#pragma unroll
            for (int nt = 0; nt < 8; nt++) {
                int col = kb * 64 + nt * 8 + 2 * tig;
                if (col     > r0g)     s[nt][0] = -1e30f;
                if (col + 1 > r0g)     s[nt][1] = -1e30f;
                if (col     > r0g + 8) s[nt][2] = -1e30f;
                if (col + 1 > r0g + 8) s[nt][3] = -1e30f;
            }
        }
        float rs0 = 0.f, rs1 = 0.f;
        uint32_t pa[4][4];
#pragma unroll
        for (int j = 0; j < 4; j++) {
            float e00 = __expf(s[2*j][0]),   e01 = __expf(s[2*j][1]);
            float e02 = __expf(s[2*j][2]),   e03 = __expf(s[2*j][3]);
            float e10 = __expf(s[2*j+1][0]), e11 = __expf(s[2*j+1][1]);
            float e12 = __expf(s[2*j+1][2]), e13 = __expf(s[2*j+1][3]);
            rs0 += (e00 + e01) + (e10 + e11);
            rs1 += (e02 + e03) + (e12 + e13);
            pa[j][0] = h2pack(e00, e01); pa[j][1] = h2pack(e02, e03);
            pa[j][2] = h2pack(e10, e11); pa[j][3] = h2pack(e12, e13);
        }
        rs0 += __shfl_xor_sync(0xffffffffu, rs0, 1);
        rs0 += __shfl_xor_sync(0xffffffffu, rs0, 2);
        rs1 += __shfl_xor_sync(0xffffffffu, rs1, 1);
        rs1 += __shfl_xor_sync(0xffffffffu, rs1, 2);
        l_[0] += rs0; l_[1] += rs1;
#pragma unroll
        for (int j = 0; j < 4; j++) {
#pragma unroll
            for (int nt = 0; nt < 16; nt++) {
                uint2 vv = Vsp[(nt * 8 + gid) * 20 + j * 4 + tig];
                uint32_t b[2] = { vv.x, vv.y };
                mma16h(o[nt], pa[j], b);
            }
        }
    }
    {
        const float il0 = 1.0f / l_[0], il1 = 1.0f / l_[1];
        const int rgO = qb * 8 + w;
#pragma unroll
        for (int j = 0; j < 8; j++) {
            int c = h * 8 + j;
            uint4 u;
            u.x = h2pack(o[2*j][0]   * il0, o[2*j][1]   * il0);
            u.y = h2pack(o[2*j][2]   * il1, o[2*j][3]   * il1);
            u.z = h2pack(o[2*j+1][0] * il0, o[2*j+1][1] * il0);
            u.w = h2pack(o[2*j+1][2] * il1, o[2*j+1][3] * il1);
            OQ[((size_t)(c * 256 + rgO) * 8 + gid) * 4 + tig] = u;
        }
    }
}

// ---------------- launch ----------------
extern "C" void kernel_launch(void* const* d_in, const int* in_sizes, int n_in,
                              void* d_out, int out_size)
{
    const float* X  = (const float*)d_in[0];
    const float* Wq = (const float*)d_in[1];
    const float* Wk = (const float*)d_in[2];
    const float* Wv = (const float*)d_in[3];
    const float* Wo = (const float*)d_in[4];
    const int*  pos = (const int*)d_in[5];
    float* out = (float*)d_out;

    uint4 *XhiQ, *XloQ, *XhQ, *WqT, *WkT, *KPp, *OQp;
    uint2 *WvT, *WoT, *VPp;
    __nv_bfloat16 *Qhi, *Qlo;
    cudaGetSymbolAddress((void**)&XhiQ, g_XhiQ);
    cudaGetSymbolAddress((void**)&XloQ, g_XloQ);
    cudaGetSymbolAddress((void**)&XhQ,  g_XhQ);
    cudaGetSymbolAddress((void**)&WqT,  g_WqT);
    cudaGetSymbolAddress((void**)&WkT,  g_WkT);
    cudaGetSymbolAddress((void**)&WvT,  g_WvT);
    cudaGetSymbolAddress((void**)&WoT,  g_WoT);
    cudaGetSymbolAddress((void**)&Qhi,  g_Qhi);
    cudaGetSymbolAddress((void**)&Qlo,  g_Qlo);
    cudaGetSymbolAddress((void**)&KPp,  g_KP);
    cudaGetSymbolAddress((void**)&VPp,  g_VP);
    cudaGetSymbolAddress((void**)&OQp,  g_OQ);

    cudaFuncSetAttribute(gemm_bf3q<1>, cudaFuncAttributeMaxDynamicSharedMemorySize, G3Q_SMEM_BYTES);
    cudaFuncSetAttribute(gemm_bf3q<2>, cudaFuncAttributeMaxDynamicSharedMemorySize, G3Q_SMEM_BYTES);
    cudaFuncSetAttribute(gemm_f16q<false>, cudaFuncAttributeMaxDynamicSharedMemorySize, F16Q_SMEM_BYTES);
    cudaFuncSetAttribute(gemm_f16q<true>, cudaFuncAttributeMaxDynamicSharedMemorySize, F16Q_SMEM_BYTES);
    cudaFuncSetAttribute(flash_mma, cudaFuncAttributeMaxDynamicSharedMemorySize, FL_SMEM_BYTES);

    // prep
    prep_XQ<<<(HID/16) * (SEQ/16) * 32 / 256, 256>>>(X, XhiQ, XloQ, XhQ);
    prep_W3<<<(HID/16) * DQTOT * 4 / 256, 256>>>(Wq, WqT, DQTOT, DQTOT - 1, 12);
    prep_W3<<<(HID/16) * DKVTOT * 4 / 256, 256>>>(Wk, WkT, DKVTOT, DKVTOT - 1, 9);
    prep_W2<<<(HID/16) * DKVTOT * 4 / 256, 256>>>(Wv, WvT, DKVTOT, DKVTOT - 1, 9);
    prep_W2<<<(DQTOT/16) * HID * 4 / 256, 256>>>(Wo, WoT, HID, HID - 1, 11);

    // projections with fused RoPE
    gemm_bf3q<1><<<dim3(NHQ, SEQ / 128), 256, G3Q_SMEM_BYTES>>>(
        XhiQ, XloQ, WqT, pos, Qhi, Qlo, nullptr, DQTOT);
    gemm_bf3q<2><<<dim3(NHKV, SEQ / 128), 256, G3Q_SMEM_BYTES>>>(
        XhiQ, XloQ, WkT, pos, nullptr, nullptr, KPp, DKVTOT);
    gemm_f16q<true><<<dim3(DKVTOT / 128, SEQ / 128), 256, F16Q_SMEM_BYTES>>>(
        XhQ, WvT, nullptr, VPp, SEQ, DKVTOT, HID);

    // attention
    flash_mma<<<dim3(SEQ / 128, NHQ), 256, FL_SMEM_BYTES>>>(
        (const uint32_t*)Qhi, (const uint32_t*)Qlo, KPp, VPp, OQp);

    // output projection
    gemm_f16q<false><<<dim3(HID / 128, SEQ / 128), 256, F16Q_SMEM_BYTES>>>(
        OQp, WoT, out, nullptr, SEQ, HID, DQTOT);
}